// round 1
// baseline (speedup 1.0000x reference)
#include <cuda_runtime.h>
#include <math.h>

#define NNODES 50000
#define NEDGES 1600000
#define DIN    512
#define HDIM   64

// ---------------- scratch (static device globals; no allocation) ----------------
__device__ float g_deg [NNODES];            // degree, then dinv (in place)
__device__ float g_norm[NEDGES];            // per-edge normalized weight
__device__ float g_bufA[NNODES * HDIM];
__device__ float g_bufB[NNODES * HDIM];
__device__ float g_bufC[NNODES * HDIM];

#define SELU_ALPHA 1.6732632423543772f
#define SELU_SCALE 1.0507009873554805f

// ---------------- small prep kernels ----------------
__global__ void k_fill_deg(float* deg) {
    int i = blockIdx.x * blockDim.x + threadIdx.x;
    if (i < NNODES) deg[i] = 1.0f;              // self-loop weight
}

__global__ void k_deg_accum(const int* __restrict__ ei,
                            const float* __restrict__ w,
                            float* __restrict__ deg) {
    int e = blockIdx.x * blockDim.x + threadIdx.x;
    if (e < NEDGES) atomicAdd(&deg[ei[NEDGES + e]], w[e]);
}

__global__ void k_dinv(float* deg) {
    int i = blockIdx.x * blockDim.x + threadIdx.x;
    if (i < NNODES) deg[i] = rsqrtf(deg[i]);    // deg >= 1 always
}

__global__ void k_norm(const int* __restrict__ ei,
                       const float* __restrict__ w,
                       const float* __restrict__ dinv,
                       float* __restrict__ norm) {
    int e = blockIdx.x * blockDim.x + threadIdx.x;
    if (e < NEDGES) norm[e] = dinv[ei[e]] * w[e] * dinv[ei[NEDGES + e]];
}

// ---------------- GEMM: [N,512] @ [512,64] -> [N,64], thread-per-node ----------------
__global__ __launch_bounds__(256) void k_gemm512(const float* __restrict__ x,
                                                 const float* __restrict__ W,
                                                 float* __restrict__ out) {
    __shared__ float sW[128 * 64];              // 32 KB chunk of W
    int node   = blockIdx.x * 256 + threadIdx.x;
    int nclamp = node < NNODES ? node : NNODES - 1;

    float acc[64];
#pragma unroll
    for (int j = 0; j < 64; j++) acc[j] = 0.0f;

    const float* xr = x + (size_t)nclamp * DIN;

    for (int kk = 0; kk < DIN; kk += 128) {
        __syncthreads();
        for (int i = threadIdx.x; i < 128 * 64; i += 256)
            sW[i] = W[kk * 64 + i];
        __syncthreads();
#pragma unroll 2
        for (int k = 0; k < 128; k++) {
            float xv = __ldg(&xr[kk + k]);
            const float4* wr = (const float4*)(sW + k * 64);
#pragma unroll
            for (int j = 0; j < 16; j++) {
                float4 w4 = wr[j];
                acc[4 * j + 0] = fmaf(xv, w4.x, acc[4 * j + 0]);
                acc[4 * j + 1] = fmaf(xv, w4.y, acc[4 * j + 1]);
                acc[4 * j + 2] = fmaf(xv, w4.z, acc[4 * j + 2]);
                acc[4 * j + 3] = fmaf(xv, w4.w, acc[4 * j + 3]);
            }
        }
    }
    if (node < NNODES) {
        float4* o = (float4*)(out + (size_t)node * 64);
#pragma unroll
        for (int j = 0; j < 16; j++)
            o[j] = make_float4(acc[4*j], acc[4*j+1], acc[4*j+2], acc[4*j+3]);
    }
}

// ---------------- dense 64x64 (optional bias / selu), thread-per-node ----------------
template <bool BIAS, bool SELU>
__global__ __launch_bounds__(256) void k_dense64(const float* __restrict__ in,
                                                 const float* __restrict__ W,
                                                 const float* __restrict__ b,
                                                 float* __restrict__ out) {
    __shared__ float sW[64 * 64];
    __shared__ float sB[64];
    int node   = blockIdx.x * 256 + threadIdx.x;
    int nclamp = node < NNODES ? node : NNODES - 1;

    for (int i = threadIdx.x; i < 64 * 64; i += 256) sW[i] = W[i];
    if (BIAS && threadIdx.x < 64) sB[threadIdx.x] = b[threadIdx.x];
    __syncthreads();

    float acc[64];
#pragma unroll
    for (int j = 0; j < 64; j++) acc[j] = 0.0f;

    const float* xr = in + (size_t)nclamp * 64;
#pragma unroll 2
    for (int k = 0; k < 64; k++) {
        float xv = __ldg(&xr[k]);
        const float4* wr = (const float4*)(sW + k * 64);
#pragma unroll
        for (int j = 0; j < 16; j++) {
            float4 w4 = wr[j];
            acc[4 * j + 0] = fmaf(xv, w4.x, acc[4 * j + 0]);
            acc[4 * j + 1] = fmaf(xv, w4.y, acc[4 * j + 1]);
            acc[4 * j + 2] = fmaf(xv, w4.z, acc[4 * j + 2]);
            acc[4 * j + 3] = fmaf(xv, w4.w, acc[4 * j + 3]);
        }
    }
    if (node < NNODES) {
        float4* o = (float4*)(out + (size_t)node * 64);
#pragma unroll
        for (int j = 0; j < 16; j++) {
            float4 v = make_float4(acc[4*j], acc[4*j+1], acc[4*j+2], acc[4*j+3]);
            if (BIAS) { v.x += sB[4*j]; v.y += sB[4*j+1]; v.z += sB[4*j+2]; v.w += sB[4*j+3]; }
            if (SELU) {
                v.x = v.x > 0.f ? SELU_SCALE * v.x : SELU_SCALE * SELU_ALPHA * expm1f(v.x);
                v.y = v.y > 0.f ? SELU_SCALE * v.y : SELU_SCALE * SELU_ALPHA * expm1f(v.y);
                v.z = v.z > 0.f ? SELU_SCALE * v.z : SELU_SCALE * SELU_ALPHA * expm1f(v.z);
                v.w = v.w > 0.f ? SELU_SCALE * v.w : SELU_SCALE * SELU_ALPHA * expm1f(v.w);
            }
            o[j] = v;
        }
    }
}

// ---------------- aggregation: self-loop init then edge scatter ----------------
__global__ void k_agg_init(const float* __restrict__ h,
                           const float* __restrict__ dinv,
                           float* __restrict__ agg) {
    int idx = blockIdx.x * blockDim.x + threadIdx.x;
    if (idx < NNODES * HDIM) {
        float d = dinv[idx >> 6];
        agg[idx] = d * d * h[idx];
    }
}

// one thread per (edge, float4-chunk): 16 chunks cover the 64-dim row
__global__ void k_scatter(const int* __restrict__ ei,
                          const float* __restrict__ norm,
                          const float* __restrict__ h,
                          float* __restrict__ agg) {
    long long idx = (long long)blockIdx.x * blockDim.x + threadIdx.x;
    if (idx >= (long long)NEDGES * 16) return;
    int e = (int)(idx >> 4);
    int c = (int)(idx & 15);
    int r   = ei[e];
    int col = ei[NEDGES + e];
    float nm = norm[e];
    float4 v = ((const float4*)h)[(size_t)r * 16 + c];
    float4* dst = (float4*)agg + (size_t)col * 16 + c;
    asm volatile("red.global.add.v4.f32 [%0], {%1,%2,%3,%4};"
                 :: "l"(dst), "f"(v.x * nm), "f"(v.y * nm), "f"(v.z * nm), "f"(v.w * nm)
                 : "memory");
}

__global__ void k_selu_bias(const float* __restrict__ agg,
                            const float* __restrict__ b,
                            float* __restrict__ out) {
    int idx = blockIdx.x * blockDim.x + threadIdx.x;
    if (idx < NNODES * HDIM) {
        float v = agg[idx] + __ldg(&b[idx & 63]);
        out[idx] = v > 0.f ? SELU_SCALE * v : SELU_SCALE * SELU_ALPHA * expm1f(v);
    }
}

// ---------------- launcher ----------------
extern "C" void kernel_launch(void* const* d_in, const int* in_sizes, int n_in,
                              void* d_out, int out_size) {
    const float* x   = (const float*)d_in[0];
    const int*   ei  = (const int*)  d_in[1];
    const float* ew  = (const float*)d_in[2];
    const float* gW1 = (const float*)d_in[3];
    const float* gb1 = (const float*)d_in[4];
    const float* gW2 = (const float*)d_in[5];
    const float* gb2 = (const float*)d_in[6];
    const float* W0  = (const float*)d_in[7];
    const float* b0  = (const float*)d_in[8];
    const float* W1  = (const float*)d_in[9];
    const float* b1  = (const float*)d_in[10];
    const float* W2  = (const float*)d_in[11];
    const float* b2  = (const float*)d_in[12];
    const float* W3  = (const float*)d_in[13];
    const float* b3  = (const float*)d_in[14];
    float* out = (float*)d_out;

    float *deg, *nrm, *bufA, *bufB, *bufC;
    cudaGetSymbolAddress((void**)&deg,  g_deg);
    cudaGetSymbolAddress((void**)&nrm,  g_norm);
    cudaGetSymbolAddress((void**)&bufA, g_bufA);
    cudaGetSymbolAddress((void**)&bufB, g_bufB);
    cudaGetSymbolAddress((void**)&bufC, g_bufC);

    const int TB = 256;
    const int gN    = (NNODES + TB - 1) / TB;
    const int gE    = (NEDGES + TB - 1) / TB;
    const int gNH   = (NNODES * HDIM + TB - 1) / TB;
    const int gScat = (int)(((long long)NEDGES * 16 + TB - 1) / TB);

    // normalization precompute
    k_fill_deg<<<gN, TB>>>(deg);
    k_deg_accum<<<gE, TB>>>(ei, ew, deg);
    k_dinv<<<gN, TB>>>(deg);
    k_norm<<<gE, TB>>>(ei, ew, deg, nrm);

    // GCN layer 1
    k_gemm512<<<gN, TB>>>(x, gW1, bufA);
    k_agg_init<<<gNH, TB>>>(bufA, deg, bufB);
    k_scatter<<<gScat, TB>>>(ei, nrm, bufA, bufB);
    k_selu_bias<<<gNH, TB>>>(bufB, gb1, bufC);

    // GCN layer 2
    k_dense64<false, false><<<gN, TB>>>(bufC, gW2, nullptr, bufA);
    k_agg_init<<<gNH, TB>>>(bufA, deg, bufB);
    k_scatter<<<gScat, TB>>>(ei, nrm, bufA, bufB);
    k_selu_bias<<<gNH, TB>>>(bufB, gb2, bufC);

    // MLP
    k_dense64<true, true ><<<gN, TB>>>(bufC, W0, b0, bufA);
    k_dense64<true, true ><<<gN, TB>>>(bufA, W1, b1, bufB);
    k_dense64<true, true ><<<gN, TB>>>(bufB, W2, b2, bufA);
    k_dense64<true, false><<<gN, TB>>>(bufA, W3, b3, out);
}

// round 2
// speedup vs baseline: 1.1733x; 1.1733x over previous
#include <cuda_runtime.h>
#include <math.h>

#define NNODES 50000
#define NEDGES 1600000
#define DIN    512
#define HDIM   64
#define BCAP   96          // per-node in-edge bucket capacity (max in-degree ~60)

// ---------------- scratch (static device globals; no allocation) ----------------
__device__ float g_deg [NNODES];                 // degree -> dinv (in place)
__device__ int   g_pos [NNODES];                 // bucket fill cursor == in-degree
__device__ int2  g_edge[(size_t)NNODES * BCAP];  // (src, norm-as-int-bits)
__device__ float g_bufA[NNODES * HDIM];
__device__ float g_bufB[NNODES * HDIM];

#define SELU_ALPHA 1.6732632423543772f
#define SELU_SCALE 1.0507009873554805f

__device__ __forceinline__ float selu_f(float v) {
    return v > 0.f ? SELU_SCALE * v : SELU_SCALE * SELU_ALPHA * expm1f(v);
}

// ---------------- prep ----------------
__global__ void k_init(float* __restrict__ deg, int* __restrict__ pos) {
    int i = blockIdx.x * blockDim.x + threadIdx.x;
    if (i < NNODES) { deg[i] = 1.0f; pos[i] = 0; }   // self-loop weight = 1
}

__global__ void k_deg_accum(const int* __restrict__ ei,
                            const float* __restrict__ w,
                            float* __restrict__ deg) {
    int e = blockIdx.x * blockDim.x + threadIdx.x;
    if (e < NEDGES) atomicAdd(&deg[ei[NEDGES + e]], w[e]);
}

__global__ void k_dinv(float* deg) {
    int i = blockIdx.x * blockDim.x + threadIdx.x;
    if (i < NNODES) deg[i] = rsqrtf(deg[i]);         // deg >= 1 always
}

// fill per-target buckets with (src, norm)
__global__ void k_fill(const int* __restrict__ ei,
                       const float* __restrict__ w,
                       const float* __restrict__ dinv,
                       int* __restrict__ pos,
                       int2* __restrict__ edge) {
    int e = blockIdx.x * blockDim.x + threadIdx.x;
    if (e >= NEDGES) return;
    int row = ei[e];
    int col = ei[NEDGES + e];
    float nm = dinv[row] * w[e] * dinv[col];
    int slot = atomicAdd(&pos[col], 1);
    if (slot < BCAP)
        edge[(size_t)col * BCAP + slot] = make_int2(row, __float_as_int(nm));
}

// ---------------- GEMM: [N,512] @ [512,64] -> [N,64], thread-per-node ----------------
__global__ __launch_bounds__(256) void k_gemm512(const float* __restrict__ x,
                                                 const float* __restrict__ W,
                                                 float* __restrict__ out) {
    __shared__ float sW[128 * 64];
    int node   = blockIdx.x * 256 + threadIdx.x;
    int nclamp = node < NNODES ? node : NNODES - 1;

    float acc[64];
#pragma unroll
    for (int j = 0; j < 64; j++) acc[j] = 0.0f;

    const float* xr = x + (size_t)nclamp * DIN;

    for (int kk = 0; kk < DIN; kk += 128) {
        __syncthreads();
        for (int i = threadIdx.x; i < 128 * 64; i += 256)
            sW[i] = W[kk * 64 + i];
        __syncthreads();
#pragma unroll 2
        for (int k = 0; k < 128; k++) {
            float xv = __ldg(&xr[kk + k]);
            const float4* wr = (const float4*)(sW + k * 64);
#pragma unroll
            for (int j = 0; j < 16; j++) {
                float4 w4 = wr[j];
                acc[4 * j + 0] = fmaf(xv, w4.x, acc[4 * j + 0]);
                acc[4 * j + 1] = fmaf(xv, w4.y, acc[4 * j + 1]);
                acc[4 * j + 2] = fmaf(xv, w4.z, acc[4 * j + 2]);
                acc[4 * j + 3] = fmaf(xv, w4.w, acc[4 * j + 3]);
            }
        }
    }
    if (node < NNODES) {
        float4* o = (float4*)(out + (size_t)node * 64);
#pragma unroll
        for (int j = 0; j < 16; j++)
            o[j] = make_float4(acc[4*j], acc[4*j+1], acc[4*j+2], acc[4*j+3]);
    }
}

// ---------------- dense 64x64 (optional bias / selu), thread-per-node ----------------
template <bool BIAS, bool SELU>
__global__ __launch_bounds__(256) void k_dense64(const float* __restrict__ in,
                                                 const float* __restrict__ W,
                                                 const float* __restrict__ b,
                                                 float* __restrict__ out) {
    __shared__ float sW[64 * 64];
    __shared__ float sB[64];
    int node   = blockIdx.x * 256 + threadIdx.x;
    int nclamp = node < NNODES ? node : NNODES - 1;

    for (int i = threadIdx.x; i < 64 * 64; i += 256) sW[i] = W[i];
    if (BIAS && threadIdx.x < 64) sB[threadIdx.x] = b[threadIdx.x];
    __syncthreads();

    float acc[64];
#pragma unroll
    for (int j = 0; j < 64; j++) acc[j] = 0.0f;

    const float* xr = in + (size_t)nclamp * 64;
#pragma unroll 2
    for (int k = 0; k < 64; k++) {
        float xv = __ldg(&xr[k]);
        const float4* wr = (const float4*)(sW + k * 64);
#pragma unroll
        for (int j = 0; j < 16; j++) {
            float4 w4 = wr[j];
            acc[4 * j + 0] = fmaf(xv, w4.x, acc[4 * j + 0]);
            acc[4 * j + 1] = fmaf(xv, w4.y, acc[4 * j + 1]);
            acc[4 * j + 2] = fmaf(xv, w4.z, acc[4 * j + 2]);
            acc[4 * j + 3] = fmaf(xv, w4.w, acc[4 * j + 3]);
        }
    }
    if (node < NNODES) {
        float4* o = (float4*)(out + (size_t)node * 64);
#pragma unroll
        for (int j = 0; j < 16; j++) {
            float4 v = make_float4(acc[4*j], acc[4*j+1], acc[4*j+2], acc[4*j+3]);
            if (BIAS) { v.x += sB[4*j]; v.y += sB[4*j+1]; v.z += sB[4*j+2]; v.w += sB[4*j+3]; }
            if (SELU) { v.x = selu_f(v.x); v.y = selu_f(v.y); v.z = selu_f(v.z); v.w = selu_f(v.w); }
            o[j] = v;
        }
    }
}

// ---------------- fused aggregation: warp-per-node CSR gather + self-loop + bias + SELU ----------------
__global__ __launch_bounds__(256) void k_gather(const float* __restrict__ h,
                                                const float* __restrict__ dinv,
                                                const int* __restrict__ pos,
                                                const int2* __restrict__ edge,
                                                const float* __restrict__ bias,
                                                float* __restrict__ out) {
    int warp = (blockIdx.x * 256 + threadIdx.x) >> 5;
    int lane = threadIdx.x & 31;
    if (warp >= NNODES) return;
    int node = warp;

    const float2* h2 = (const float2*)h;

    // self-loop: dinv^2 * h[node]
    float d = __ldg(&dinv[node]);
    float2 acc = h2[(size_t)node * 32 + lane];
    acc.x *= d * d; acc.y *= d * d;

    int cnt = __ldg(&pos[node]);
    if (cnt > BCAP) cnt = BCAP;
    const int2* eb = edge + (size_t)node * BCAP;

    for (int i = 0; i < cnt; i++) {
        int2 er = __ldg(&eb[i]);                  // broadcast LDG.64
        float nm = __int_as_float(er.y);
        float2 hv = h2[(size_t)er.x * 32 + lane]; // coalesced 256B gather
        acc.x = fmaf(nm, hv.x, acc.x);
        acc.y = fmaf(nm, hv.y, acc.y);
    }

    float2 bb = ((const float2*)bias)[lane];
    acc.x = selu_f(acc.x + bb.x);
    acc.y = selu_f(acc.y + bb.y);
    ((float2*)out)[(size_t)node * 32 + lane] = acc;
}

// ---------------- launcher ----------------
extern "C" void kernel_launch(void* const* d_in, const int* in_sizes, int n_in,
                              void* d_out, int out_size) {
    const float* x   = (const float*)d_in[0];
    const int*   ei  = (const int*)  d_in[1];
    const float* ew  = (const float*)d_in[2];
    const float* gW1 = (const float*)d_in[3];
    const float* gb1 = (const float*)d_in[4];
    const float* gW2 = (const float*)d_in[5];
    const float* gb2 = (const float*)d_in[6];
    const float* W0  = (const float*)d_in[7];
    const float* b0  = (const float*)d_in[8];
    const float* W1  = (const float*)d_in[9];
    const float* b1  = (const float*)d_in[10];
    const float* W2  = (const float*)d_in[11];
    const float* b2  = (const float*)d_in[12];
    const float* W3  = (const float*)d_in[13];
    const float* b3  = (const float*)d_in[14];
    float* out = (float*)d_out;

    float *deg, *bufA, *bufB; int *pos; int2 *edge;
    cudaGetSymbolAddress((void**)&deg,  g_deg);
    cudaGetSymbolAddress((void**)&pos,  g_pos);
    cudaGetSymbolAddress((void**)&edge, g_edge);
    cudaGetSymbolAddress((void**)&bufA, g_bufA);
    cudaGetSymbolAddress((void**)&bufB, g_bufB);

    const int TB = 256;
    const int gN  = (NNODES + TB - 1) / TB;
    const int gE  = (NEDGES + TB - 1) / TB;
    const int gW  = (NNODES * 32 + TB - 1) / TB;   // warp per node

    // CSR-bucket build (shared by both GCN layers)
    k_init<<<gN, TB>>>(deg, pos);
    k_deg_accum<<<gE, TB>>>(ei, ew, deg);
    k_dinv<<<gN, TB>>>(deg);
    k_fill<<<gE, TB>>>(ei, ew, deg, pos, edge);

    // GCN layer 1
    k_gemm512<<<gN, TB>>>(x, gW1, bufA);
    k_gather<<<gW, TB>>>(bufA, deg, pos, edge, gb1, bufB);

    // GCN layer 2
    k_dense64<false, false><<<gN, TB>>>(bufB, gW2, nullptr, bufA);
    k_gather<<<gW, TB>>>(bufA, deg, pos, edge, gb2, bufB);

    // MLP
    k_dense64<true, true ><<<gN, TB>>>(bufB, W0, b0, bufA);
    k_dense64<true, true ><<<gN, TB>>>(bufA, W1, b1, bufB);
    k_dense64<true, true ><<<gN, TB>>>(bufB, W2, b2, bufA);
    k_dense64<true, false><<<gN, TB>>>(bufA, W3, b3, out);
}

// round 3
// speedup vs baseline: 1.6952x; 1.4448x over previous
#include <cuda_runtime.h>
#include <math.h>

#define NNODES 50000
#define NEDGES 1600000
#define DIN    512
#define HDIM   64
#define BCAP   96          // max in-degree for 1.6M uniform edges into 50k bins ~57

typedef unsigned long long u64;

// ---------------- scratch (static device globals; no allocation) ----------------
__device__ float g_deg [NNODES];                 // degree -> dinv (in place)
__device__ int   g_pos [NNODES];                 // bucket fill cursor == in-degree
__device__ int2  g_edge[(size_t)NNODES * BCAP];  // (src, raw-weight-bits)
__device__ float g_bufA[NNODES * HDIM];
__device__ float g_bufB[NNODES * HDIM];

#define SELU_ALPHA 1.6732632423543772f
#define SELU_SCALE 1.0507009873554805f

__device__ __forceinline__ float selu_f(float v) {
    return v > 0.f ? SELU_SCALE * v : SELU_SCALE * SELU_ALPHA * expm1f(v);
}

// ---- Blackwell packed fp32x2 helpers ----
__device__ __forceinline__ u64 pack2(float x) {
    u64 r; asm("mov.b64 %0, {%1, %1};" : "=l"(r) : "f"(x)); return r;
}
__device__ __forceinline__ void fma2(u64& d, u64 a, u64 b) {
    asm("fma.rn.f32x2 %0, %1, %2, %0;" : "+l"(d) : "l"(a), "l"(b));
}
__device__ __forceinline__ float2 unpack2(u64 v) {
    float2 f; asm("mov.b64 {%0, %1}, %2;" : "=f"(f.x), "=f"(f.y) : "l"(v)); return f;
}

// ---------------- prep ----------------
__global__ void k_init(float* __restrict__ deg, int* __restrict__ pos) {
    int i = blockIdx.x * blockDim.x + threadIdx.x;
    if (i < NNODES) { deg[i] = 1.0f; pos[i] = 0; }   // self-loop weight = 1
}

// single edge pass: degree accumulation + bucket fill with raw weights
__global__ void k_build(const int* __restrict__ ei,
                        const float* __restrict__ w,
                        float* __restrict__ deg,
                        int* __restrict__ pos,
                        int2* __restrict__ edge) {
    int e = blockIdx.x * blockDim.x + threadIdx.x;
    if (e >= NEDGES) return;
    int row = ei[e];
    int col = ei[NEDGES + e];
    float we = w[e];
    atomicAdd(&deg[col], we);
    int slot = atomicAdd(&pos[col], 1);
    if (slot < BCAP)
        edge[(size_t)col * BCAP + slot] = make_int2(row, __float_as_int(we));
}

__global__ void k_dinv(float* deg) {
    int i = blockIdx.x * blockDim.x + threadIdx.x;
    if (i < NNODES) deg[i] = rsqrtf(deg[i]);         // deg >= 1 always
}

// ---------------- GEMM1: [N,512]@[512,64], epilogue scales by dinv ----------------
__global__ __launch_bounds__(256) void k_gemm512(const float* __restrict__ x,
                                                 const float* __restrict__ W,
                                                 const float* __restrict__ dinv,
                                                 float* __restrict__ out) {
    __shared__ float sW[128 * 64];
    int node   = blockIdx.x * 256 + threadIdx.x;
    int nclamp = node < NNODES ? node : NNODES - 1;

    u64 acc[32];
#pragma unroll
    for (int j = 0; j < 32; j++) acc[j] = 0ull;

    const float4* xr = (const float4*)(x + (size_t)nclamp * DIN);

    for (int kk = 0; kk < DIN; kk += 128) {
        __syncthreads();
        {
            const float4* Wc = (const float4*)(W + kk * 64);
            float4* s4 = (float4*)sW;
            for (int i = threadIdx.x; i < 128 * 16; i += 256) s4[i] = Wc[i];
        }
        __syncthreads();
#pragma unroll 2
        for (int k4 = 0; k4 < 32; k4++) {
            float4 xv = __ldg(&xr[(kk >> 2) + k4]);
            float xs[4] = {xv.x, xv.y, xv.z, xv.w};
#pragma unroll
            for (int s = 0; s < 4; s++) {
                u64 xx = pack2(xs[s]);
                const ulonglong2* wr = (const ulonglong2*)(sW + (k4 * 4 + s) * 64);
#pragma unroll
                for (int j = 0; j < 16; j++) {
                    ulonglong2 wv = wr[j];
                    fma2(acc[2 * j + 0], xx, wv.x);
                    fma2(acc[2 * j + 1], xx, wv.y);
                }
            }
        }
    }
    if (node < NNODES) {
        float d = __ldg(&dinv[node]);
        float2* o = (float2*)(out + (size_t)node * 64);
#pragma unroll
        for (int j = 0; j < 32; j++) {
            float2 f = unpack2(acc[j]);
            o[j] = make_float2(f.x * d, f.y * d);
        }
    }
}

// ---------------- dense 64x64, epilogue scales by dinv (GCN layer 2 transform) ----------------
__global__ __launch_bounds__(256) void k_dense64s(const float* __restrict__ in,
                                                  const float* __restrict__ W,
                                                  const float* __restrict__ dinv,
                                                  float* __restrict__ out) {
    __shared__ float sW[64 * 64];
    int node   = blockIdx.x * 256 + threadIdx.x;
    int nclamp = node < NNODES ? node : NNODES - 1;

    {
        const float4* Wc = (const float4*)W;
        float4* s4 = (float4*)sW;
        for (int i = threadIdx.x; i < 64 * 16; i += 256) s4[i] = Wc[i];
    }
    __syncthreads();

    u64 acc[32];
#pragma unroll
    for (int j = 0; j < 32; j++) acc[j] = 0ull;

    const float* xr = in + (size_t)nclamp * 64;
#pragma unroll 4
    for (int k = 0; k < 64; k++) {
        u64 xx = pack2(__ldg(&xr[k]));
        const ulonglong2* wr = (const ulonglong2*)(sW + k * 64);
#pragma unroll
        for (int j = 0; j < 16; j++) {
            ulonglong2 wv = wr[j];
            fma2(acc[2 * j + 0], xx, wv.x);
            fma2(acc[2 * j + 1], xx, wv.y);
        }
    }
    if (node < NNODES) {
        float d = __ldg(&dinv[node]);
        float2* o = (float2*)(out + (size_t)node * 64);
#pragma unroll
        for (int j = 0; j < 32; j++) {
            float2 f = unpack2(acc[j]);
            o[j] = make_float2(f.x * d, f.y * d);
        }
    }
}

// ---------------- fused 2-layer 64x64 MLP (bias + selu per layer) ----------------
template <bool SELU_B>
__global__ __launch_bounds__(256) void k_mlp2(const float* __restrict__ in,
                                              const float* __restrict__ Wa,
                                              const float* __restrict__ ba,
                                              const float* __restrict__ Wb,
                                              const float* __restrict__ bb,
                                              float* __restrict__ out) {
    __shared__ float sW[2 * 64 * 64];
    __shared__ float sB[2][64];
    int node   = blockIdx.x * 256 + threadIdx.x;
    int nclamp = node < NNODES ? node : NNODES - 1;

    {
        const float4* WA = (const float4*)Wa;
        const float4* WB = (const float4*)Wb;
        float4* s4 = (float4*)sW;
        for (int i = threadIdx.x; i < 64 * 16; i += 256) { s4[i] = WA[i]; s4[64 * 16 + i] = WB[i]; }
        if (threadIdx.x < 64)       sB[0][threadIdx.x]      = ba[threadIdx.x];
        else if (threadIdx.x < 128) sB[1][threadIdx.x - 64] = bb[threadIdx.x - 64];
    }
    __syncthreads();

    float vin[64];
    {
        const float4* xr = (const float4*)(in + (size_t)nclamp * 64);
#pragma unroll
        for (int j = 0; j < 16; j++) {
            float4 v = __ldg(&xr[j]);
            vin[4*j] = v.x; vin[4*j+1] = v.y; vin[4*j+2] = v.z; vin[4*j+3] = v.w;
        }
    }

#pragma unroll
    for (int layer = 0; layer < 2; layer++) {
        u64 acc[32];
#pragma unroll
        for (int j = 0; j < 32; j++) acc[j] = 0ull;
        const float* Wbase = sW + layer * 64 * 64;
#pragma unroll 4
        for (int k = 0; k < 64; k++) {
            u64 xx = pack2(vin[k]);
            const ulonglong2* wr = (const ulonglong2*)(Wbase + k * 64);
#pragma unroll
            for (int j = 0; j < 16; j++) {
                ulonglong2 wv = wr[j];
                fma2(acc[2 * j + 0], xx, wv.x);
                fma2(acc[2 * j + 1], xx, wv.y);
            }
        }
        bool do_selu = (layer == 0) || SELU_B;
#pragma unroll
        for (int j = 0; j < 32; j++) {
            float2 f = unpack2(acc[j]);
            f.x += sB[layer][2 * j];
            f.y += sB[layer][2 * j + 1];
            if (do_selu) { f.x = selu_f(f.x); f.y = selu_f(f.y); }
            vin[2 * j] = f.x; vin[2 * j + 1] = f.y;
        }
    }

    if (node < NNODES) {
        float4* o = (float4*)(out + (size_t)node * 64);
#pragma unroll
        for (int j = 0; j < 16; j++)
            o[j] = make_float4(vin[4*j], vin[4*j+1], vin[4*j+2], vin[4*j+3]);
    }
}

// ---------------- warp-per-node gather: out = selu(dinv*(sum w*h'[src] + h'[node]) + b) ----------------
__global__ __launch_bounds__(256) void k_gather(const float* __restrict__ h,
                                                const float* __restrict__ dinv,
                                                const int* __restrict__ pos,
                                                const int2* __restrict__ edge,
                                                const float* __restrict__ bias,
                                                float* __restrict__ out) {
    int warp = (blockIdx.x * 256 + threadIdx.x) >> 5;
    int lane = threadIdx.x & 31;
    if (warp >= NNODES) return;
    int node = warp;

    const u64* h2 = (const u64*)h;

    u64 acc = h2[(size_t)node * 32 + lane];          // self term: h'[node]

    int cnt = __ldg(&pos[node]);
    if (cnt > BCAP) cnt = BCAP;
    const int4* eb4 = (const int4*)(edge + (size_t)node * BCAP);   // 16B-aligned (BCAP*8 % 16 == 0)

    int pairs = cnt >> 1;
    for (int i = 0; i < pairs; i++) {
        int4 er = __ldg(&eb4[i]);                    // two edge records, one LDG.128
        u64 h0 = __ldg(&h2[(size_t)er.x * 32 + lane]);
        u64 h1 = __ldg(&h2[(size_t)er.z * 32 + lane]);
        fma2(acc, pack2(__int_as_float(er.y)), h0);
        fma2(acc, pack2(__int_as_float(er.w)), h1);
    }
    if (cnt & 1) {
        int2 er = __ldg(&((const int2*)eb4)[cnt - 1]);
        u64 hv = __ldg(&h2[(size_t)er.x * 32 + lane]);
        fma2(acc, pack2(__int_as_float(er.y)), hv);
    }

    float d  = __ldg(&dinv[node]);
    float2 a = unpack2(acc);
    float2 bb = ((const float2*)bias)[lane];
    a.x = selu_f(fmaf(d, a.x, bb.x));
    a.y = selu_f(fmaf(d, a.y, bb.y));
    ((float2*)out)[(size_t)node * 32 + lane] = a;
}

// ---------------- launcher ----------------
extern "C" void kernel_launch(void* const* d_in, const int* in_sizes, int n_in,
                              void* d_out, int out_size) {
    const float* x   = (const float*)d_in[0];
    const int*   ei  = (const int*)  d_in[1];
    const float* ew  = (const float*)d_in[2];
    const float* gW1 = (const float*)d_in[3];
    const float* gb1 = (const float*)d_in[4];
    const float* gW2 = (const float*)d_in[5];
    const float* gb2 = (const float*)d_in[6];
    const float* W0  = (const float*)d_in[7];
    const float* b0  = (const float*)d_in[8];
    const float* W1  = (const float*)d_in[9];
    const float* b1  = (const float*)d_in[10];
    const float* W2  = (const float*)d_in[11];
    const float* b2  = (const float*)d_in[12];
    const float* W3  = (const float*)d_in[13];
    const float* b3  = (const float*)d_in[14];
    float* out = (float*)d_out;

    float *deg, *bufA, *bufB; int *pos; int2 *edge;
    cudaGetSymbolAddress((void**)&deg,  g_deg);
    cudaGetSymbolAddress((void**)&pos,  g_pos);
    cudaGetSymbolAddress((void**)&edge, g_edge);
    cudaGetSymbolAddress((void**)&bufA, g_bufA);
    cudaGetSymbolAddress((void**)&bufB, g_bufB);

    const int TB = 256;
    const int gN = (NNODES + TB - 1) / TB;
    const int gE = (NEDGES + TB - 1) / TB;
    const int gW = (NNODES * 32 + TB - 1) / TB;   // warp per node

    // bucket + degree build (one edge pass), shared by both GCN layers
    k_init <<<gN, TB>>>(deg, pos);
    k_build<<<gE, TB>>>(ei, ew, deg, pos, edge);
    k_dinv <<<gN, TB>>>(deg);

    // GCN layer 1 (h' = dinv * xW folded into GEMM epilogue)
    k_gemm512<<<gN, TB>>>(x, gW1, deg, bufA);
    k_gather <<<gW, TB>>>(bufA, deg, pos, edge, gb1, bufB);

    // GCN layer 2
    k_dense64s<<<gN, TB>>>(bufB, gW2, deg, bufA);
    k_gather  <<<gW, TB>>>(bufA, deg, pos, edge, gb2, bufB);

    // MLP (two fused 2-layer kernels)
    k_mlp2<true ><<<gN, TB>>>(bufB, W0, b0, W1, b1, bufA);
    k_mlp2<false><<<gN, TB>>>(bufA, W2, b2, W3, b3, out);
}

// round 6
// speedup vs baseline: 2.8038x; 1.6539x over previous
#include <cuda_runtime.h>
#include <math.h>

#define NNODES 50000
#define NEDGES 1600000
#define DIN    512
#define HDIM   64
#define BCAP   96          // max in-degree for 1.6M uniform edges into 50k bins ~57

typedef unsigned long long u64;

// ---------------- scratch (static device globals; no allocation) ----------------
__device__ float g_deg [NNODES];                 // degree -> dinv (in place)
__device__ int   g_pos [NNODES];                 // bucket fill cursor == in-degree
__device__ int2  g_edge[(size_t)NNODES * BCAP];  // (src, raw-weight-bits)
__device__ float g_bufA[NNODES * HDIM];
__device__ float g_bufB[NNODES * HDIM];

#define SELU_ALPHA 1.6732632423543772f
#define SELU_SCALE 1.0507009873554805f

__device__ __forceinline__ float selu_f(float v) {
    return v > 0.f ? SELU_SCALE * v : SELU_SCALE * SELU_ALPHA * expm1f(v);
}

// ---- Blackwell packed fp32x2 helpers ----
__device__ __forceinline__ u64 pack2(float x) {
    u64 r; asm("mov.b64 %0, {%1, %1};" : "=l"(r) : "f"(x)); return r;
}
__device__ __forceinline__ void fma2(u64& d, u64 a, u64 b) {
    asm("fma.rn.f32x2 %0, %1, %2, %0;" : "+l"(d) : "l"(a), "l"(b));
}
__device__ __forceinline__ float2 unpack2(u64 v) {
    float2 f; asm("mov.b64 {%0, %1}, %2;" : "=f"(f.x), "=f"(f.y) : "l"(v)); return f;
}

// ---------------- prep ----------------
__global__ void k_init(float* __restrict__ deg, int* __restrict__ pos) {
    int i = blockIdx.x * blockDim.x + threadIdx.x;
    if (i < NNODES) { deg[i] = 1.0f; pos[i] = 0; }   // self-loop weight = 1
}

__global__ void k_build(const int* __restrict__ ei,
                        const float* __restrict__ w,
                        float* __restrict__ deg,
                        int* __restrict__ pos,
                        int2* __restrict__ edge) {
    int e = blockIdx.x * blockDim.x + threadIdx.x;
    if (e >= NEDGES) return;
    int row = ei[e];
    int col = ei[NEDGES + e];
    float we = w[e];
    atomicAdd(&deg[col], we);
    int slot = atomicAdd(&pos[col], 1);
    if (slot < BCAP)
        edge[(size_t)col * BCAP + slot] = make_int2(row, __float_as_int(we));
}

__global__ void k_dinv(float* deg) {
    int i = blockIdx.x * blockDim.x + threadIdx.x;
    if (i < NNODES) deg[i] = rsqrtf(deg[i]);         // deg >= 1 always
}

// =====================================================================
// Tiled GEMM1: [N,512]@[512,64] -> dinv * result
// block = 128 nodes x 64 cols, 256 thr (16x16), thread tile 8 rows x 4 cols
// =====================================================================
__global__ __launch_bounds__(256) void k_gemm512_t(const float* __restrict__ x,
                                                   const float* __restrict__ W,
                                                   const float* __restrict__ dinv,
                                                   float* __restrict__ out) {
    __shared__ float sX[128 * 32];   // node-major [row][32]
    __shared__ float sW[32 * 64];    // k-major   [k][64]

    int tid = threadIdx.x;
    int tx = tid & 15;               // col group: cols tx*4 .. tx*4+3
    int ty = tid >> 4;               // row group: rows ty*8 .. ty*8+7
    int nb = blockIdx.x * 128;

    u64 acc[8][2];
#pragma unroll
    for (int i = 0; i < 8; i++) { acc[i][0] = 0ull; acc[i][1] = 0ull; }

    const float4* x4 = (const float4*)x;
    const float4* W4 = (const float4*)W;
    float4* sX4 = (float4*)sX;
    float4* sW4 = (float4*)sW;

    for (int kt = 0; kt < 16; kt++) {
        __syncthreads();
        // x-tile: 128 rows x 8 float4
#pragma unroll
        for (int p = 0; p < 4; p++) {
            int f   = tid + p * 256;
            int row = f >> 3, kq = f & 7;
            int node = nb + row; if (node >= NNODES) node = NNODES - 1;
            sX4[row * 8 + kq] = __ldg(&x4[(size_t)node * 128 + kt * 8 + kq]);
        }
        // W-tile: 32x64 = 512 float4 (contiguous chunk)
        sW4[tid]       = __ldg(&W4[kt * 512 + tid]);
        sW4[tid + 256] = __ldg(&W4[kt * 512 + tid + 256]);
        __syncthreads();

#pragma unroll
        for (int kc = 0; kc < 8; kc++) {
            float4 a4[8];
#pragma unroll
            for (int i = 0; i < 8; i++)
                a4[i] = sX4[(ty * 8 + i) * 8 + kc];
#pragma unroll
            for (int j = 0; j < 4; j++) {
                ulonglong2 b = *(const ulonglong2*)(sW + (kc * 4 + j) * 64 + tx * 4);
#pragma unroll
                for (int i = 0; i < 8; i++) {
                    float av = j == 0 ? a4[i].x : j == 1 ? a4[i].y : j == 2 ? a4[i].z : a4[i].w;
                    u64 ap = pack2(av);
                    fma2(acc[i][0], ap, b.x);
                    fma2(acc[i][1], ap, b.y);
                }
            }
        }
    }

#pragma unroll
    for (int i = 0; i < 8; i++) {
        int node = nb + ty * 8 + i;
        if (node < NNODES) {
            float d = __ldg(&dinv[node]);
            float2 f0 = unpack2(acc[i][0]);
            float2 f1 = unpack2(acc[i][1]);
            ((float4*)(out + (size_t)node * 64))[tx] =
                make_float4(f0.x * d, f0.y * d, f1.x * d, f1.y * d);
        }
    }
}

// =====================================================================
// Tiled dense 64x64 with dinv epilogue (GCN layer-2 transform)
// =====================================================================
__global__ __launch_bounds__(256) void k_dense64_t(const float* __restrict__ in,
                                                   const float* __restrict__ W,
                                                   const float* __restrict__ dinv,
                                                   float* __restrict__ out) {
    __shared__ float sX[128 * 64];   // 32 KB
    __shared__ float sW[64 * 64];    // 16 KB

    int tid = threadIdx.x;
    int tx = tid & 15, ty = tid >> 4;
    int nb = blockIdx.x * 128;

    const float4* in4 = (const float4*)in;
    const float4* W4  = (const float4*)W;
    float4* sX4 = (float4*)sX;
    float4* sW4 = (float4*)sW;

#pragma unroll
    for (int p = 0; p < 8; p++) {
        int f = tid + p * 256;
        int row = f >> 4, q = f & 15;
        int node = nb + row; if (node >= NNODES) node = NNODES - 1;
        sX4[row * 16 + q] = __ldg(&in4[(size_t)node * 16 + q]);
    }
#pragma unroll
    for (int p = 0; p < 4; p++)
        sW4[tid + p * 256] = __ldg(&W4[tid + p * 256]);
    __syncthreads();

    u64 acc[8][2];
#pragma unroll
    for (int i = 0; i < 8; i++) { acc[i][0] = 0ull; acc[i][1] = 0ull; }

#pragma unroll
    for (int kc = 0; kc < 16; kc++) {
        float4 a4[8];
#pragma unroll
        for (int i = 0; i < 8; i++)
            a4[i] = sX4[(ty * 8 + i) * 16 + kc];
#pragma unroll
        for (int j = 0; j < 4; j++) {
            ulonglong2 b = *(const ulonglong2*)(sW + (kc * 4 + j) * 64 + tx * 4);
#pragma unroll
            for (int i = 0; i < 8; i++) {
                float av = j == 0 ? a4[i].x : j == 1 ? a4[i].y : j == 2 ? a4[i].z : a4[i].w;
                u64 ap = pack2(av);
                fma2(acc[i][0], ap, b.x);
                fma2(acc[i][1], ap, b.y);
            }
        }
    }

#pragma unroll
    for (int i = 0; i < 8; i++) {
        int node = nb + ty * 8 + i;
        if (node < NNODES) {
            float d = __ldg(&dinv[node]);
            float2 f0 = unpack2(acc[i][0]);
            float2 f1 = unpack2(acc[i][1]);
            ((float4*)(out + (size_t)node * 64))[tx] =
                make_float4(f0.x * d, f0.y * d, f1.x * d, f1.y * d);
        }
    }
}

// =====================================================================
// Tiled fused 2-layer MLP: selu(x@Wa+ba) then (@Wb+bb) [selu optional]
// single 16KB weight buffer time-multiplexed; activations stay in smem.
// smem total = 32KB + 16KB = 48KB exact.
// =====================================================================
template <bool SELU_B>
__global__ __launch_bounds__(256) void k_mlp2_t(const float* __restrict__ in,
                                                const float* __restrict__ Wa,
                                                const float* __restrict__ ba,
                                                const float* __restrict__ Wb,
                                                const float* __restrict__ bb,
                                                float* __restrict__ out) {
    __shared__ float sX[128 * 64];   // 32 KB activations
    __shared__ float sW[64 * 64];    // 16 KB current-layer weights

    int tid = threadIdx.x;
    int tx = tid & 15, ty = tid >> 4;
    int nb = blockIdx.x * 128;

    const float4* in4 = (const float4*)in;
    const float4* WA4 = (const float4*)Wa;
    const float4* WB4 = (const float4*)Wb;
    float4* sX4 = (float4*)sX;
    float4* sW4 = (float4*)sW;

    // biases for this thread's 4 columns (registers, no smem)
    float4 bA = __ldg(&((const float4*)ba)[tx]);
    float4 bB = __ldg(&((const float4*)bb)[tx]);

#pragma unroll
    for (int p = 0; p < 8; p++) {
        int f = tid + p * 256;
        int row = f >> 4, q = f & 15;
        int node = nb + row; if (node >= NNODES) node = NNODES - 1;
        sX4[row * 16 + q] = __ldg(&in4[(size_t)node * 16 + q]);
    }
#pragma unroll
    for (int p = 0; p < 4; p++)
        sW4[tid + p * 256] = __ldg(&WA4[tid + p * 256]);
    __syncthreads();

    // ---------------- layer A ----------------
    u64 acc[8][2];
#pragma unroll
    for (int i = 0; i < 8; i++) { acc[i][0] = 0ull; acc[i][1] = 0ull; }

#pragma unroll
    for (int kc = 0; kc < 16; kc++) {
        float4 a4[8];
#pragma unroll
        for (int i = 0; i < 8; i++)
            a4[i] = sX4[(ty * 8 + i) * 16 + kc];
#pragma unroll
        for (int j = 0; j < 4; j++) {
            ulonglong2 b = *(const ulonglong2*)(sW + (kc * 4 + j) * 64 + tx * 4);
#pragma unroll
            for (int i = 0; i < 8; i++) {
                float av = j == 0 ? a4[i].x : j == 1 ? a4[i].y : j == 2 ? a4[i].z : a4[i].w;
                u64 ap = pack2(av);
                fma2(acc[i][0], ap, b.x);
                fma2(acc[i][1], ap, b.y);
            }
        }
    }

    __syncthreads();   // all reads of sX (layer A) and sW (Wa) complete

    // write selu activations back to sX; reload Wb into sW
#pragma unroll
    for (int i = 0; i < 8; i++) {
        float2 f0 = unpack2(acc[i][0]);
        float2 f1 = unpack2(acc[i][1]);
        float4 v = make_float4(selu_f(f0.x + bA.x), selu_f(f0.y + bA.y),
                               selu_f(f1.x + bA.z), selu_f(f1.y + bA.w));
        sX4[(ty * 8 + i) * 16 + tx] = v;
    }
#pragma unroll
    for (int p = 0; p < 4; p++)
        sW4[tid + p * 256] = __ldg(&WB4[tid + p * 256]);
    __syncthreads();

    // ---------------- layer B ----------------
#pragma unroll
    for (int i = 0; i < 8; i++) { acc[i][0] = 0ull; acc[i][1] = 0ull; }

#pragma unroll
    for (int kc = 0; kc < 16; kc++) {
        float4 a4[8];
#pragma unroll
        for (int i = 0; i < 8; i++)
            a4[i] = sX4[(ty * 8 + i) * 16 + kc];
#pragma unroll
        for (int j = 0; j < 4; j++) {
            ulonglong2 b = *(const ulonglong2*)(sW + (kc * 4 + j) * 64 + tx * 4);
#pragma unroll
            for (int i = 0; i < 8; i++) {
                float av = j == 0 ? a4[i].x : j == 1 ? a4[i].y : j == 2 ? a4[i].z : a4[i].w;
                u64 ap = pack2(av);
                fma2(acc[i][0], ap, b.x);
                fma2(acc[i][1], ap, b.y);
            }
        }
    }

#pragma unroll
    for (int i = 0; i < 8; i++) {
        int node = nb + ty * 8 + i;
        if (node < NNODES) {
            float2 f0 = unpack2(acc[i][0]);
            float2 f1 = unpack2(acc[i][1]);
            float4 v = make_float4(f0.x + bB.x, f0.y + bB.y, f1.x + bB.z, f1.y + bB.w);
            if (SELU_B) { v.x = selu_f(v.x); v.y = selu_f(v.y); v.z = selu_f(v.z); v.w = selu_f(v.w); }
            ((float4*)(out + (size_t)node * 64))[tx] = v;
        }
    }
}

// ---------------- warp-per-node gather: out = selu(dinv*(sum w*h'[src] + h'[node]) + b) ----------------
__global__ __launch_bounds__(256) void k_gather(const float* __restrict__ h,
                                                const float* __restrict__ dinv,
                                                const int* __restrict__ pos,
                                                const int2* __restrict__ edge,
                                                const float* __restrict__ bias,
                                                float* __restrict__ out) {
    int warp = (blockIdx.x * 256 + threadIdx.x) >> 5;
    int lane = threadIdx.x & 31;
    if (warp >= NNODES) return;
    int node = warp;

    const u64* h2 = (const u64*)h;

    u64 acc = h2[(size_t)node * 32 + lane];          // self term: h'[node]

    int cnt = __ldg(&pos[node]);
    if (cnt > BCAP) cnt = BCAP;
    const int4* eb4 = (const int4*)(edge + (size_t)node * BCAP);

    int pairs = cnt >> 1;
    for (int i = 0; i < pairs; i++) {
        int4 er = __ldg(&eb4[i]);
        u64 h0 = __ldg(&h2[(size_t)er.x * 32 + lane]);
        u64 h1 = __ldg(&h2[(size_t)er.z * 32 + lane]);
        fma2(acc, pack2(__int_as_float(er.y)), h0);
        fma2(acc, pack2(__int_as_float(er.w)), h1);
    }
    if (cnt & 1) {
        int2 er = __ldg(&((const int2*)eb4)[cnt - 1]);
        u64 hv = __ldg(&h2[(size_t)er.x * 32 + lane]);
        fma2(acc, pack2(__int_as_float(er.y)), hv);
    }

    float d  = __ldg(&dinv[node]);
    float2 a = unpack2(acc);
    float2 bb = ((const float2*)bias)[lane];
    a.x = selu_f(fmaf(d, a.x, bb.x));
    a.y = selu_f(fmaf(d, a.y, bb.y));
    ((float2*)out)[(size_t)node * 32 + lane] = a;
}

// ---------------- launcher ----------------
extern "C" void kernel_launch(void* const* d_in, const int* in_sizes, int n_in,
                              void* d_out, int out_size) {
    const float* x   = (const float*)d_in[0];
    const int*   ei  = (const int*)  d_in[1];
    const float* ew  = (const float*)d_in[2];
    const float* gW1 = (const float*)d_in[3];
    const float* gb1 = (const float*)d_in[4];
    const float* gW2 = (const float*)d_in[5];
    const float* gb2 = (const float*)d_in[6];
    const float* W0  = (const float*)d_in[7];
    const float* b0  = (const float*)d_in[8];
    const float* W1  = (const float*)d_in[9];
    const float* b1  = (const float*)d_in[10];
    const float* W2  = (const float*)d_in[11];
    const float* b2  = (const float*)d_in[12];
    const float* W3  = (const float*)d_in[13];
    const float* b3  = (const float*)d_in[14];
    float* out = (float*)d_out;

    float *deg, *bufA, *bufB; int *pos; int2 *edge;
    cudaGetSymbolAddress((void**)&deg,  g_deg);
    cudaGetSymbolAddress((void**)&pos,  g_pos);
    cudaGetSymbolAddress((void**)&edge, g_edge);
    cudaGetSymbolAddress((void**)&bufA, g_bufA);
    cudaGetSymbolAddress((void**)&bufB, g_bufB);

    const int TB = 256;
    const int gN = (NNODES + TB - 1) / TB;
    const int gE = (NEDGES + TB - 1) / TB;
    const int gW = (NNODES * 32 + TB - 1) / TB;     // warp per node
    const int gT = (NNODES + 127) / 128;            // 128-node tiles

    // bucket + degree build (one edge pass), shared by both GCN layers
    k_init <<<gN, TB>>>(deg, pos);
    k_build<<<gE, TB>>>(ei, ew, deg, pos, edge);
    k_dinv <<<gN, TB>>>(deg);

    // GCN layer 1 (h' = dinv * xW folded into GEMM epilogue)
    k_gemm512_t<<<gT, TB>>>(x, gW1, deg, bufA);
    k_gather   <<<gW, TB>>>(bufA, deg, pos, edge, gb1, bufB);

    // GCN layer 2
    k_dense64_t<<<gT, TB>>>(bufB, gW2, deg, bufA);
    k_gather   <<<gW, TB>>>(bufA, deg, pos, edge, gb2, bufB);

    // MLP (two fused 2-layer kernels)
    k_mlp2_t<true ><<<gT, TB>>>(bufB, W0, b0, W1, b1, bufA);
    k_mlp2_t<false><<<gT, TB>>>(bufA, W2, b2, W3, b3, out);
}

// round 8
// speedup vs baseline: 2.9993x; 1.0697x over previous
#include <cuda_runtime.h>
#include <stdint.h>
#include <math.h>

#define NNODES 50000
#define NEDGES 1600000
#define DIN    512
#define HDIM   64
#define BCAP   96          // max in-degree for 1.6M uniform edges into 50k bins ~57

typedef unsigned long long u64;

// ---------------- scratch (static device globals; no allocation) ----------------
__device__ float g_deg [NNODES];                 // degree -> dinv (in place)
__device__ int   g_pos [NNODES];                 // bucket fill cursor == in-degree
__device__ int2  g_edge[(size_t)NNODES * BCAP];  // (src, raw-weight-bits)
__device__ float g_bufA[NNODES * HDIM];
__device__ float g_bufB[NNODES * HDIM];

#define SELU_ALPHA 1.6732632423543772f
#define SELU_SCALE 1.0507009873554805f

__device__ __forceinline__ float selu_f(float v) {
    return v > 0.f ? SELU_SCALE * v : SELU_SCALE * SELU_ALPHA * expm1f(v);
}

// ---- Blackwell packed fp32x2 helpers ----
__device__ __forceinline__ u64 pack2(float x) {
    u64 r; asm("mov.b64 %0, {%1, %1};" : "=l"(r) : "f"(x)); return r;
}
__device__ __forceinline__ void fma2(u64& d, u64 a, u64 b) {
    asm("fma.rn.f32x2 %0, %1, %2, %0;" : "+l"(d) : "l"(a), "l"(b));
}
__device__ __forceinline__ float2 unpack2(u64 v) {
    float2 f; asm("mov.b64 {%0, %1}, %2;" : "=f"(f.x), "=f"(f.y) : "l"(v)); return f;
}

// ---- cp.async helpers ----
__device__ __forceinline__ void cp16(uint32_t dst, const void* src) {
    asm volatile("cp.async.cg.shared.global [%0], [%1], 16;" :: "r"(dst), "l"(src));
}
__device__ __forceinline__ void cp_commit() {
    asm volatile("cp.async.commit_group;");
}

// ---------------- prep ----------------
__global__ void k_init(float* __restrict__ deg, int* __restrict__ pos) {
    int i = blockIdx.x * blockDim.x + threadIdx.x;
    if (i < NNODES) { deg[i] = 1.0f; pos[i] = 0; }   // self-loop weight = 1
}

__global__ void k_build(const int* __restrict__ ei,
                        const float* __restrict__ w,
                        float* __restrict__ deg,
                        int* __restrict__ pos,
                        int2* __restrict__ edge) {
    int e = blockIdx.x * blockDim.x + threadIdx.x;
    if (e >= NEDGES) return;
    int row = ei[e];
    int col = ei[NEDGES + e];
    float we = w[e];
    atomicAdd(&deg[col], we);
    int slot = atomicAdd(&pos[col], 1);
    if (slot < BCAP)
        edge[(size_t)col * BCAP + slot] = make_int2(row, __float_as_int(we));
}

__global__ void k_dinv(float* deg) {
    int i = blockIdx.x * blockDim.x + threadIdx.x;
    if (i < NNODES) deg[i] = rsqrtf(deg[i]);         // deg >= 1 always
}

// =====================================================================
// Tiled GEMM1: [N,512]@[512,64] -> dinv * result
// cp.async double-buffered pipeline; smem = 2*(16KB X + 8KB W) = 48KB exact
// =====================================================================
__global__ __launch_bounds__(256) void k_gemm512_t(const float* __restrict__ x,
                                                   const float* __restrict__ W,
                                                   const float* __restrict__ dinv,
                                                   float* __restrict__ out) {
    __shared__ float sX[2][128 * 32];   // node-major [row][32]
    __shared__ float sW[2][32 * 64];    // k-major   [k][64]

    int tid = threadIdx.x;
    int tx = tid & 15;               // col group: cols tx*4 .. tx*4+3
    int ty = tid >> 4;               // row group: rows ty*8 .. ty*8+7
    int nb = blockIdx.x * 128;

    const float4* x4 = (const float4*)x;
    const float4* W4 = (const float4*)W;

    // per-thread load slots: 4 x-chunks + 2 w-chunks per tile
    const float4* xsrc[4];
    uint32_t xoff[4];
#pragma unroll
    for (int p = 0; p < 4; p++) {
        int f   = tid + p * 256;
        int row = f >> 3, kq = f & 7;
        int node = nb + row; if (node >= NNODES) node = NNODES - 1;
        xsrc[p] = &x4[(size_t)node * 128 + kq];        // advance by kt*8 per tile
        xoff[p] = (uint32_t)((row * 8 + kq) * 16);
    }
    uint32_t sx0 = (uint32_t)__cvta_generic_to_shared(&sX[0][0]);
    uint32_t sw0 = (uint32_t)__cvta_generic_to_shared(&sW[0][0]);

    u64 acc[8][2];
#pragma unroll
    for (int i = 0; i < 8; i++) { acc[i][0] = 0ull; acc[i][1] = 0ull; }

    // issue loads for tile kt into buffer b
    auto issue = [&](int kt, int b) {
        uint32_t xb = sx0 + b * 16384;
        uint32_t wb = sw0 + b * 8192;
#pragma unroll
        for (int p = 0; p < 4; p++)
            cp16(xb + xoff[p], xsrc[p] + kt * 8);
        cp16(wb + tid * 16,         W4 + kt * 512 + tid);
        cp16(wb + (tid + 256) * 16, W4 + kt * 512 + tid + 256);
        cp_commit();
    };

    issue(0, 0);   // prologue

    for (int kt = 0; kt < 16; kt++) {
        int cur = kt & 1;
        if (kt < 15) {
            issue(kt + 1, cur ^ 1);
            asm volatile("cp.async.wait_group 1;");
        } else {
            asm volatile("cp.async.wait_group 0;");
        }
        __syncthreads();

        const float4* sX4 = (const float4*)sX[cur];
        const float*  sWb = sW[cur];
#pragma unroll
        for (int kc = 0; kc < 8; kc++) {
            float4 a4[8];
#pragma unroll
            for (int i = 0; i < 8; i++)
                a4[i] = sX4[(ty * 8 + i) * 8 + kc];
#pragma unroll
            for (int j = 0; j < 4; j++) {
                ulonglong2 b = *(const ulonglong2*)(sWb + (kc * 4 + j) * 64 + tx * 4);
#pragma unroll
                for (int i = 0; i < 8; i++) {
                    float av = j == 0 ? a4[i].x : j == 1 ? a4[i].y : j == 2 ? a4[i].z : a4[i].w;
                    u64 ap = pack2(av);
                    fma2(acc[i][0], ap, b.x);
                    fma2(acc[i][1], ap, b.y);
                }
            }
        }
        __syncthreads();
    }

#pragma unroll
    for (int i = 0; i < 8; i++) {
        int node = nb + ty * 8 + i;
        if (node < NNODES) {
            float d = __ldg(&dinv[node]);
            float2 f0 = unpack2(acc[i][0]);
            float2 f1 = unpack2(acc[i][1]);
            ((float4*)(out + (size_t)node * 64))[tx] =
                make_float4(f0.x * d, f0.y * d, f1.x * d, f1.y * d);
        }
    }
}

// =====================================================================
// Tiled dense 64x64 with dinv epilogue (GCN layer-2 transform)
// =====================================================================
__global__ __launch_bounds__(256) void k_dense64_t(const float* __restrict__ in,
                                                   const float* __restrict__ W,
                                                   const float* __restrict__ dinv,
                                                   float* __restrict__ out) {
    __shared__ float sX[128 * 64];   // 32 KB
    __shared__ float sW[64 * 64];    // 16 KB

    int tid = threadIdx.x;
    int tx = tid & 15, ty = tid >> 4;
    int nb = blockIdx.x * 128;

    const float4* in4 = (const float4*)in;
    const float4* W4  = (const float4*)W;
    float4* sX4 = (float4*)sX;
    float4* sW4 = (float4*)sW;

#pragma unroll
    for (int p = 0; p < 8; p++) {
        int f = tid + p * 256;
        int row = f >> 4, q = f & 15;
        int node = nb + row; if (node >= NNODES) node = NNODES - 1;
        sX4[row * 16 + q] = __ldg(&in4[(size_t)node * 16 + q]);
    }
#pragma unroll
    for (int p = 0; p < 4; p++)
        sW4[tid + p * 256] = __ldg(&W4[tid + p * 256]);
    __syncthreads();

    u64 acc[8][2];
#pragma unroll
    for (int i = 0; i < 8; i++) { acc[i][0] = 0ull; acc[i][1] = 0ull; }

#pragma unroll
    for (int kc = 0; kc < 16; kc++) {
        float4 a4[8];
#pragma unroll
        for (int i = 0; i < 8; i++)
            a4[i] = sX4[(ty * 8 + i) * 16 + kc];
#pragma unroll
        for (int j = 0; j < 4; j++) {
            ulonglong2 b = *(const ulonglong2*)(sW + (kc * 4 + j) * 64 + tx * 4);
#pragma unroll
            for (int i = 0; i < 8; i++) {
                float av = j == 0 ? a4[i].x : j == 1 ? a4[i].y : j == 2 ? a4[i].z : a4[i].w;
                u64 ap = pack2(av);
                fma2(acc[i][0], ap, b.x);
                fma2(acc[i][1], ap, b.y);
            }
        }
    }

#pragma unroll
    for (int i = 0; i < 8; i++) {
        int node = nb + ty * 8 + i;
        if (node < NNODES) {
            float d = __ldg(&dinv[node]);
            float2 f0 = unpack2(acc[i][0]);
            float2 f1 = unpack2(acc[i][1]);
            ((float4*)(out + (size_t)node * 64))[tx] =
                make_float4(f0.x * d, f0.y * d, f1.x * d, f1.y * d);
        }
    }
}

// =====================================================================
// Tiled fused 2-layer MLP: selu(x@Wa+ba) then (@Wb+bb) [selu optional]
// single 16KB weight buffer time-multiplexed; activations stay in smem.
// =====================================================================
template <bool SELU_B>
__global__ __launch_bounds__(256) void k_mlp2_t(const float* __restrict__ in,
                                                const float* __restrict__ Wa,
                                                const float* __restrict__ ba,
                                                const float* __restrict__ Wb,
                                                const float* __restrict__ bb,
                                                float* __restrict__ out) {
    __shared__ float sX[128 * 64];   // 32 KB activations
    __shared__ float sW[64 * 64];    // 16 KB current-layer weights

    int tid = threadIdx.x;
    int tx = tid & 15, ty = tid >> 4;
    int nb = blockIdx.x * 128;

    const float4* in4 = (const float4*)in;
    const float4* WA4 = (const float4*)Wa;
    const float4* WB4 = (const float4*)Wb;
    float4* sX4 = (float4*)sX;
    float4* sW4 = (float4*)sW;

    float4 bA = __ldg(&((const float4*)ba)[tx]);
    float4 bB = __ldg(&((const float4*)bb)[tx]);

#pragma unroll
    for (int p = 0; p < 8; p++) {
        int f = tid + p * 256;
        int row = f >> 4, q = f & 15;
        int node = nb + row; if (node >= NNODES) node = NNODES - 1;
        sX4[row * 16 + q] = __ldg(&in4[(size_t)node * 16 + q]);
    }
#pragma unroll
    for (int p = 0; p < 4; p++)
        sW4[tid + p * 256] = __ldg(&WA4[tid + p * 256]);
    __syncthreads();

    // ---------------- layer A ----------------
    u64 acc[8][2];
#pragma unroll
    for (int i = 0; i < 8; i++) { acc[i][0] = 0ull; acc[i][1] = 0ull; }

#pragma unroll
    for (int kc = 0; kc < 16; kc++) {
        float4 a4[8];
#pragma unroll
        for (int i = 0; i < 8; i++)
            a4[i] = sX4[(ty * 8 + i) * 16 + kc];
#pragma unroll
        for (int j = 0; j < 4; j++) {
            ulonglong2 b = *(const ulonglong2*)(sW + (kc * 4 + j) * 64 + tx * 4);
#pragma unroll
            for (int i = 0; i < 8; i++) {
                float av = j == 0 ? a4[i].x : j == 1 ? a4[i].y : j == 2 ? a4[i].z : a4[i].w;
                u64 ap = pack2(av);
                fma2(acc[i][0], ap, b.x);
                fma2(acc[i][1], ap, b.y);
            }
        }
    }

    __syncthreads();   // all reads of sX (layer A) and sW (Wa) complete

#pragma unroll
    for (int i = 0; i < 8; i++) {
        float2 f0 = unpack2(acc[i][0]);
        float2 f1 = unpack2(acc[i][1]);
        float4 v = make_float4(selu_f(f0.x + bA.x), selu_f(f0.y + bA.y),
                               selu_f(f1.x + bA.z), selu_f(f1.y + bA.w));
        sX4[(ty * 8 + i) * 16 + tx] = v;
    }
#pragma unroll
    for (int p = 0; p < 4; p++)
        sW4[tid + p * 256] = __ldg(&WB4[tid + p * 256]);
    __syncthreads();

    // ---------------- layer B ----------------
#pragma unroll
    for (int i = 0; i < 8; i++) { acc[i][0] = 0ull; acc[i][1] = 0ull; }

#pragma unroll
    for (int kc = 0; kc < 16; kc++) {
        float4 a4[8];
#pragma unroll
        for (int i = 0; i < 8; i++)
            a4[i] = sX4[(ty * 8 + i) * 16 + kc];
#pragma unroll
        for (int j = 0; j < 4; j++) {
            ulonglong2 b = *(const ulonglong2*)(sW + (kc * 4 + j) * 64 + tx * 4);
#pragma unroll
            for (int i = 0; i < 8; i++) {
                float av = j == 0 ? a4[i].x : j == 1 ? a4[i].y : j == 2 ? a4[i].z : a4[i].w;
                u64 ap = pack2(av);
                fma2(acc[i][0], ap, b.x);
                fma2(acc[i][1], ap, b.y);
            }
        }
    }

#pragma unroll
    for (int i = 0; i < 8; i++) {
        int node = nb + ty * 8 + i;
        if (node < NNODES) {
            float2 f0 = unpack2(acc[i][0]);
            float2 f1 = unpack2(acc[i][1]);
            float4 v = make_float4(f0.x + bB.x, f0.y + bB.y, f1.x + bB.z, f1.y + bB.w);
            if (SELU_B) { v.x = selu_f(v.x); v.y = selu_f(v.y); v.z = selu_f(v.z); v.w = selu_f(v.w); }
            ((float4*)(out + (size_t)node * 64))[tx] = v;
        }
    }
}

// ---------------- warp-per-node gather: out = selu(dinv*(sum w*h'[src] + h'[node]) + b) ----------------
__global__ __launch_bounds__(256) void k_gather(const float* __restrict__ h,
                                                const float* __restrict__ dinv,
                                                const int* __restrict__ pos,
                                                const int2* __restrict__ edge,
                                                const float* __restrict__ bias,
                                                float* __restrict__ out) {
    int warp = (blockIdx.x * 256 + threadIdx.x) >> 5;
    int lane = threadIdx.x & 31;
    if (warp >= NNODES) return;
    int node = warp;

    const u64* h2 = (const u64*)h;

    u64 acc = h2[(size_t)node * 32 + lane];          // self term: h'[node]

    int cnt = __ldg(&pos[node]);
    if (cnt > BCAP) cnt = BCAP;
    const int4* eb4 = (const int4*)(edge + (size_t)node * BCAP);

    int pairs = cnt >> 1;
    for (int i = 0; i < pairs; i++) {
        int4 er = __ldg(&eb4[i]);
        u64 h0 = __ldg(&h2[(size_t)er.x * 32 + lane]);
        u64 h1 = __ldg(&h2[(size_t)er.z * 32 + lane]);
        fma2(acc, pack2(__int_as_float(er.y)), h0);
        fma2(acc, pack2(__int_as_float(er.w)), h1);
    }
    if (cnt & 1) {
        int2 er = __ldg(&((const int2*)eb4)[cnt - 1]);
        u64 hv = __ldg(&h2[(size_t)er.x * 32 + lane]);
        fma2(acc, pack2(__int_as_float(er.y)), hv);
    }

    float d  = __ldg(&dinv[node]);
    float2 a = unpack2(acc);
    float2 bb = ((const float2*)bias)[lane];
    a.x = selu_f(fmaf(d, a.x, bb.x));
    a.y = selu_f(fmaf(d, a.y, bb.y));
    ((float2*)out)[(size_t)node * 32 + lane] = a;
}

// ---------------- launcher ----------------
extern "C" void kernel_launch(void* const* d_in, const int* in_sizes, int n_in,
                              void* d_out, int out_size) {
    const float* x   = (const float*)d_in[0];
    const int*   ei  = (const int*)  d_in[1];
    const float* ew  = (const float*)d_in[2];
    const float* gW1 = (const float*)d_in[3];
    const float* gb1 = (const float*)d_in[4];
    const float* gW2 = (const float*)d_in[5];
    const float* gb2 = (const float*)d_in[6];
    const float* W0  = (const float*)d_in[7];
    const float* b0  = (const float*)d_in[8];
    const float* W1  = (const float*)d_in[9];
    const float* b1  = (const float*)d_in[10];
    const float* W2  = (const float*)d_in[11];
    const float* b2  = (const float*)d_in[12];
    const float* W3  = (const float*)d_in[13];
    const float* b3  = (const float*)d_in[14];
    float* out = (float*)d_out;

    float *deg, *bufA, *bufB; int *pos; int2 *edge;
    cudaGetSymbolAddress((void**)&deg,  g_deg);
    cudaGetSymbolAddress((void**)&pos,  g_pos);
    cudaGetSymbolAddress((void**)&edge, g_edge);
    cudaGetSymbolAddress((void**)&bufA, g_bufA);
    cudaGetSymbolAddress((void**)&bufB, g_bufB);

    const int TB = 256;
    const int gN = (NNODES + TB - 1) / TB;
    const int gE = (NEDGES + TB - 1) / TB;
    const int gW = (NNODES * 32 + TB - 1) / TB;     // warp per node
    const int gT = (NNODES + 127) / 128;            // 128-node tiles

    // bucket + degree build (one edge pass), shared by both GCN layers
    k_init <<<gN, TB>>>(deg, pos);
    k_build<<<gE, TB>>>(ei, ew, deg, pos, edge);
    k_dinv <<<gN, TB>>>(deg);

    // GCN layer 1 (h' = dinv * xW folded into GEMM epilogue)
    k_gemm512_t<<<gT, TB>>>(x, gW1, deg, bufA);
    k_gather   <<<gW, TB>>>(bufA, deg, pos, edge, gb1, bufB);

    // GCN layer 2
    k_dense64_t<<<gT, TB>>>(bufB, gW2, deg, bufA);
    k_gather   <<<gW, TB>>>(bufA, deg, pos, edge, gb2, bufB);

    // MLP (two fused 2-layer kernels)
    k_mlp2_t<true ><<<gT, TB>>>(bufB, W0, b0, W1, b1, bufA);
    k_mlp2_t<false><<<gT, TB>>>(bufA, W2, b2, W3, b3, out);
}